// round 4
// baseline (speedup 1.0000x reference)
#include <cuda_runtime.h>
#include <cuda_bf16.h>
#include <math.h>

// Problem constants
#define BB 32
#define TT 32
#define SS 64
#define HH 512
#define EE 512
#define VV 32000
#define T1 (TT-1)
#define TBV ((size_t)T1*BB*VV)
#define BH (BB*HH)
#define MPAD 1024         // ah rows padded 992 -> 1024

// -------- persistent device scratch --------
__device__ float g_h[BH];
__device__ float g_c[BH];
__device__ float g_proj[BB*SS*HH];
__device__ float g_Gpart[6*BB*4*HH];
__device__ float g_ah_all[T1*BH];
__device__ float g_zero[BH];
__device__ int   g_argmax[T1*BB];
__device__ float g_logits[T1*BB*VV];                       // fallback, 127MB
__device__ __align__(16) __nv_bfloat16 g_Wh[(size_t)VV*HH];
__device__ __align__(16) __nv_bfloat16 g_Wl[(size_t)VV*HH];
__device__ __align__(16) __nv_bfloat16 g_Ah[MPAD*HH];
__device__ __align__(16) __nv_bfloat16 g_Al[MPAD*HH];

__device__ __forceinline__ float sigf(float x){ return 1.0f/(1.0f+expf(-x)); }

// fast exp via FMA polynomial (no MUFU in hot loops)
__device__ __forceinline__ float fexp(float x){
    float t = x * 1.4426950408889634f;
    float n = rintf(t);
    float f = t - n;
    float p = 1.5403530e-4f;
    p = fmaf(p, f, 1.3333558e-3f);
    p = fmaf(p, f, 9.6181291e-3f);
    p = fmaf(p, f, 5.5504109e-2f);
    p = fmaf(p, f, 2.4022651e-1f);
    p = fmaf(p, f, 6.9314718e-1f);
    p = fmaf(p, f, 1.0f);
    int e = (int)n;
    e = e < -126 ? -126 : (e > 127 ? 127 : e);
    float sc = __int_as_float((e+127)<<23);
    return p*sc;
}

// ------------------ low-level helpers (sm_80-compatible PTX) ------------------
__device__ __forceinline__ unsigned smem_u32(const void* p){
    unsigned a;
    asm("{ .reg .u64 t; cvta.to.shared.u64 t, %1; cvt.u32.u64 %0, t; }" : "=r"(a) : "l"(p));
    return a;
}
__device__ __forceinline__ void cpa16(unsigned dst, const void* src){
    asm volatile("cp.async.cg.shared.global [%0], [%1], 16;" :: "r"(dst), "l"(src));
}
#define CP_COMMIT() asm volatile("cp.async.commit_group;" ::: "memory")
#define CP_WAIT(n)  asm volatile("cp.async.wait_group %0;" :: "n"(n) : "memory")

__device__ __forceinline__ void ldmx4(unsigned* r, unsigned addr){
    asm volatile("ldmatrix.sync.aligned.m8n8.x4.shared.b16 {%0,%1,%2,%3}, [%4];"
        : "=r"(r[0]), "=r"(r[1]), "=r"(r[2]), "=r"(r[3]) : "r"(addr));
}
__device__ __forceinline__ void mma16816(float* d, const unsigned* a,
                                         unsigned b0, unsigned b1){
    asm volatile(
        "mma.sync.aligned.m16n8k16.row.col.f32.bf16.bf16.f32 "
        "{%0,%1,%2,%3}, {%4,%5,%6,%7}, {%8,%9}, {%0,%1,%2,%3};"
        : "+f"(d[0]), "+f"(d[1]), "+f"(d[2]), "+f"(d[3])
        : "r"(a[0]), "r"(a[1]), "r"(a[2]), "r"(a[3]), "r"(b0), "r"(b1));
}

// ---------------------------------------------------------------------------
// Generic tiled SGEMM (used only for proj precompute)
// ---------------------------------------------------------------------------
template<int BM,int BN,int BK,int TM,int TN>
__global__ void sgemm(const float* __restrict__ A, const float* __restrict__ B,
                      float* __restrict__ C, int M, int N, int K)
{
    constexpr int THREADS = (BM/TM)*(BN/TN);
    static_assert(THREADS == 256, "256 threads expected");
    __shared__ float As[BK][BM+4];
    __shared__ float Bs[BK][BN+4];
    const int tid = threadIdx.x;
    const int bm = blockIdx.y*BM, bn = blockIdx.x*BN;
    const int tx = tid % (BN/TN);
    const int ty = tid / (BN/TN);
    float acc[TM][TN];
    #pragma unroll
    for (int i=0;i<TM;i++)
        #pragma unroll
        for (int j=0;j<TN;j++) acc[i][j]=0.f;

    for (int k0 = 0; k0 < K; k0 += BK) {
        #pragma unroll
        for (int i=0;i<(BM*BK)/THREADS;i++){
            int idx = tid + i*THREADS; int m = idx/BK, k = idx%BK;
            As[k][m] = A[(size_t)(bm+m)*K + k0 + k];
        }
        #pragma unroll
        for (int i=0;i<(BN*BK)/THREADS;i++){
            int idx = tid + i*THREADS; int n = idx/BK, k = idx%BK;
            Bs[k][n] = B[(size_t)(bn+n)*K + k0 + k];
        }
        __syncthreads();
        #pragma unroll
        for (int kk=0;kk<BK;kk++){
            float a[TM], b[TN];
            #pragma unroll
            for (int i=0;i<TM;i++) a[i] = As[kk][ty*TM+i];
            #pragma unroll
            for (int j=0;j<TN;j++) b[j] = Bs[kk][tx*TN+j];
            #pragma unroll
            for (int i=0;i<TM;i++)
                #pragma unroll
                for (int j=0;j<TN;j++) acc[i][j] += a[i]*b[j];
        }
        __syncthreads();
    }
    #pragma unroll
    for (int i=0;i<TM;i++){
        int gm = bm + ty*TM + i;
        #pragma unroll
        for (int j=0;j<TN;j++)
            C[(size_t)gm*N + bn + tx*TN + j] = acc[i][j];
    }
}

// ---------------------------------------------------------------------------
// Gates GEMM (per step t), split-K=6: partials into g_Gpart
// ---------------------------------------------------------------------------
__global__ void k_gates(const int* __restrict__ tgt,
                        const float* __restrict__ emb,
                        const float* __restrict__ W_ih,
                        const float* __restrict__ W_hh,
                        const float* __restrict__ ahp,
                        int t)
{
    constexpr int BM=32, BN=64, BK=16, TM=2, TN=4, THREADS=256;
    __shared__ float As[BK][BM+4];
    __shared__ float Bs[BK][BN+4];
    __shared__ int   ws[BB];
    const int tid = threadIdx.x;
    const int bn = blockIdx.x * BN;
    const int kbeg = blockIdx.z * (1536/6);
    const int tx = tid % (BN/TN);
    const int ty = tid / (BN/TN);
    if (tid < BB) ws[tid] = tgt[tid*TT + t];
    float acc[TM][TN];
    #pragma unroll
    for (int i=0;i<TM;i++)
        #pragma unroll
        for (int j=0;j<TN;j++) acc[i][j]=0.f;
    __syncthreads();

    for (int k0 = kbeg; k0 < kbeg + 256; k0 += BK) {
        #pragma unroll
        for (int i=0;i<(BM*BK)/THREADS;i++){
            int idx = tid + i*THREADS; int m = idx/BK, k = idx%BK;
            int kg = k0 + k;
            float v;
            if (kg < EE)            v = emb[(size_t)ws[m]*EE + kg];
            else if (kg < EE+HH)    v = ahp[m*HH + (kg-EE)];
            else                    v = g_h[m*HH + (kg-EE-HH)];
            As[k][m] = v;
        }
        #pragma unroll
        for (int i=0;i<(BN*BK)/THREADS;i++){
            int idx = tid + i*THREADS; int n = idx/BK, k = idx%BK;
            int j = bn + n; int kg = k0 + k;
            Bs[k][n] = (kg < EE+HH) ? W_ih[(size_t)j*(EE+HH) + kg]
                                    : W_hh[(size_t)j*HH + (kg-EE-HH)];
        }
        __syncthreads();
        #pragma unroll
        for (int kk=0;kk<BK;kk++){
            float a[TM], b[TN];
            #pragma unroll
            for (int i=0;i<TM;i++) a[i] = As[kk][ty*TM+i];
            #pragma unroll
            for (int j=0;j<TN;j++) b[j] = Bs[kk][tx*TN+j];
            #pragma unroll
            for (int i=0;i<TM;i++)
                #pragma unroll
                for (int j=0;j<TN;j++) acc[i][j] += a[i]*b[j];
        }
        __syncthreads();
    }
    #pragma unroll
    for (int i=0;i<TM;i++){
        int b = ty*TM + i;
        #pragma unroll
        for (int j=0;j<TN;j++){
            int n = bn + tx*TN + j;
            g_Gpart[(size_t)blockIdx.z*BB*4*HH + b*4*HH + n] = acc[i][j];
        }
    }
}

// ---------------------------------------------------------------------------
// Fused per-step: LSTM cell + attention + ah2 GEMM + tanh
// 32 blocks (one per batch) x 512 threads.
// ---------------------------------------------------------------------------
__global__ void k_step(const float* __restrict__ b_ih, const float* __restrict__ b_hh,
                       const int* __restrict__ lens, const float* __restrict__ enc,
                       const float* __restrict__ W_c, const float* __restrict__ b_c,
                       int t)
{
    __shared__ float xc[2*HH];     // [h2(512) | ctx(512)]
    __shared__ float sc[SS];
    const int b   = blockIdx.x;
    const int tid = threadIdx.x;   // = h index
    const int len = lens[b];
    const int w = tid >> 5, l = tid & 31;

    // ---- LSTM cell ----
    float gv[4];
    #pragma unroll
    for (int q=0;q<4;q++){
        int j = q*HH + tid;
        float s = b_ih[j] + b_hh[j];
        #pragma unroll
        for (int z=0;z<6;z++) s += g_Gpart[(size_t)z*BB*4*HH + b*4*HH + j];
        gv[q] = s;
    }
    int idx = b*HH + tid;
    float ig = sigf(gv[0]);
    float fg = sigf(gv[1]);
    float gg = tanhf(gv[2]);
    float og = sigf(gv[3]);
    float c  = fg * g_c[idx] + ig * gg;
    g_c[idx] = c;
    float h2 = og * tanhf(c);
    g_h[idx] = h2;
    xc[tid] = h2;
    __syncthreads();

    // ---- attention scores ----
    for (int s = w; s < SS; s += 16) {
        const float* pr = &g_proj[((size_t)s*BB + b)*HH];
        float sum = 0.f;
        for (int k = l; k < HH; k += 32) sum += xc[k] * pr[k];
        #pragma unroll
        for (int off=16; off>0; off>>=1) sum += __shfl_xor_sync(0xffffffffu, sum, off);
        if (l == 0) sc[s] = (s < len) ? sum : -1e9f;
    }
    __syncthreads();

    if (tid < 32) {
        float v0 = sc[tid], v1 = sc[tid+32];
        float m = fmaxf(v0, v1);
        #pragma unroll
        for (int off=16; off>0; off>>=1) m = fmaxf(m, __shfl_xor_sync(0xffffffffu, m, off));
        float e0 = expf(v0 - m), e1 = expf(v1 - m);
        float s = e0 + e1;
        #pragma unroll
        for (int off=16; off>0; off>>=1) s += __shfl_xor_sync(0xffffffffu, s, off);
        float inv = 1.0f / s;
        sc[tid]    = e0 * inv;
        sc[tid+32] = e1 * inv;
    }
    __syncthreads();

    // ---- context ----
    float acc = 0.f;
    #pragma unroll 4
    for (int s = 0; s < SS; s++)
        acc += sc[s] * enc[((size_t)s*BB + b)*HH + tid];
    xc[HH + tid] = acc;
    __syncthreads();

    // ---- ah2 = tanh([h2|ctx] @ W_c^T + b_c) ----
    // warp w computes outputs n = w*32 .. w*32+31, coalesced W_c reads
    float* dst = g_ah_all + (size_t)t*BH + b*HH;
    for (int j = 0; j < 32; j++){
        int n = w*32 + j;
        const float* wr = W_c + (size_t)n*(2*HH);
        float s = 0.f;
        #pragma unroll
        for (int q = 0; q < 32; q++)
            s += xc[l + q*32] * wr[l + q*32];
        #pragma unroll
        for (int off=16; off>0; off>>=1) s += __shfl_xor_sync(0xffffffffu, s, off);
        if (l == 0) dst[n] = tanhf(s + b_c[n]);
    }
}

__global__ void k_init(const float* __restrict__ h0, const float* __restrict__ c0)
{
    int idx = blockIdx.x*blockDim.x + threadIdx.x;
    if (idx >= BH) return;
    g_h[idx] = h0[idx];
    g_c[idx] = c0[idx];
}

// ---------------------------------------------------------------------------
// bf16 split-precision conversions
// ---------------------------------------------------------------------------
__global__ void k_convW(const float* __restrict__ W)
{
    size_t i = ((size_t)blockIdx.x*256 + threadIdx.x)*4;
    if (i >= (size_t)VV*HH) return;
    float4 v = *(const float4*)(W + i);
    __nv_bfloat16 h0 = __float2bfloat16(v.x);
    __nv_bfloat16 h1 = __float2bfloat16(v.y);
    __nv_bfloat16 h2 = __float2bfloat16(v.z);
    __nv_bfloat16 h3 = __float2bfloat16(v.w);
    __nv_bfloat16 l0 = __float2bfloat16(v.x - __bfloat162float(h0));
    __nv_bfloat16 l1 = __float2bfloat16(v.y - __bfloat162float(h1));
    __nv_bfloat16 l2 = __float2bfloat16(v.z - __bfloat162float(h2));
    __nv_bfloat16 l3 = __float2bfloat16(v.w - __bfloat162float(h3));
    *(__nv_bfloat162*)(g_Wh + i)     = __nv_bfloat162(h0, h1);
    *(__nv_bfloat162*)(g_Wh + i + 2) = __nv_bfloat162(h2, h3);
    *(__nv_bfloat162*)(g_Wl + i)     = __nv_bfloat162(l0, l1);
    *(__nv_bfloat162*)(g_Wl + i + 2) = __nv_bfloat162(l2, l3);
}

__global__ void k_convA()
{
    size_t i = ((size_t)blockIdx.x*256 + threadIdx.x)*4;
    if (i >= (size_t)MPAD*HH) return;
    int row = (int)(i >> 9);
    float4 v;
    if (row < T1*BB) v = *(const float4*)(g_ah_all + i);
    else             v = make_float4(0.f,0.f,0.f,0.f);
    __nv_bfloat16 h0 = __float2bfloat16(v.x);
    __nv_bfloat16 h1 = __float2bfloat16(v.y);
    __nv_bfloat16 h2 = __float2bfloat16(v.z);
    __nv_bfloat16 h3 = __float2bfloat16(v.w);
    __nv_bfloat16 l0 = __float2bfloat16(v.x - __bfloat162float(h0));
    __nv_bfloat16 l1 = __float2bfloat16(v.y - __bfloat162float(h1));
    __nv_bfloat16 l2 = __float2bfloat16(v.z - __bfloat162float(h2));
    __nv_bfloat16 l3 = __float2bfloat16(v.w - __bfloat162float(h3));
    *(__nv_bfloat162*)(g_Ah + i)     = __nv_bfloat162(h0, h1);
    *(__nv_bfloat162*)(g_Ah + i + 2) = __nv_bfloat162(h2, h3);
    *(__nv_bfloat162*)(g_Al + i)     = __nv_bfloat162(l0, l1);
    *(__nv_bfloat162*)(g_Al + i + 2) = __nv_bfloat162(l2, l3);
}

// ---------------------------------------------------------------------------
// Vocab GEMM via mma.sync (HMMA bf16, fp32 accum), 3-term split precision.
// C[992,32000] = A[992,512] @ W[32000,512]^T + b_o
// BM=128, BN=64, BK=32, 256 threads (8 warps, 4x2), cp.async double-buffered.
// grid (8 mtiles, 500 ntiles) so B-sharing CTAs are adjacent in launch order.
// ---------------------------------------------------------------------------
#define VK_STR 40   // padded smem row stride (bf16 elems)

__global__ void __launch_bounds__(256, 2)
k_vocab(const float* __restrict__ b_o, float* __restrict__ logits)
{
    __shared__ __align__(16) __nv_bfloat16 As[2][128*VK_STR];
    __shared__ __align__(16) __nv_bfloat16 Bs[2][64*VK_STR];
    const int tid  = threadIdx.x;
    const int wid  = tid >> 5, lane = tid & 31;
    const int mtile = blockIdx.x;   // 0..7
    const int ntile = blockIdx.y;   // 0..499

    const __nv_bfloat16* Ap[3] = { g_Ah + (size_t)mtile*128*HH,
                                   g_Ah + (size_t)mtile*128*HH,
                                   g_Al + (size_t)mtile*128*HH };
    const __nv_bfloat16* Bp[3] = { g_Wh + (size_t)ntile*64*HH,
                                   g_Wl + (size_t)ntile*64*HH,
                                   g_Wh + (size_t)ntile*64*HH };

    const unsigned sA0 = smem_u32(&As[0][0]);
    const unsigned sA1 = smem_u32(&As[1][0]);
    const unsigned sB0 = smem_u32(&Bs[0][0]);
    const unsigned sB1 = smem_u32(&Bs[1][0]);

    // A: 512 16B-chunks (2/thread); B: 256 (1/thread)
    const int aid0 = tid, aid1 = tid + 256;
    const int ar0 = aid0 >> 2, ac0 = (aid0 & 3) * 8;
    const int ar1 = aid1 >> 2, ac1 = (aid1 & 3) * 8;
    const int br  = tid >> 2,  bc  = (tid & 3) * 8;

    auto issue = [&](int buf, int ch){
        int pass = ch >> 4;
        int k0   = (ch & 15) * 32;
        unsigned sa = buf ? sA1 : sA0;
        unsigned sb = buf ? sB1 : sB0;
        const __nv_bfloat16* a = Ap[pass] + k0;
        const __nv_bfloat16* bsrc = Bp[pass] + k0;
        cpa16(sa + (unsigned)(ar0*VK_STR + ac0)*2, a + (size_t)ar0*HH + ac0);
        cpa16(sa + (unsigned)(ar1*VK_STR + ac1)*2, a + (size_t)ar1*HH + ac1);
        cpa16(sb + (unsigned)(br *VK_STR + bc )*2, bsrc + (size_t)br*HH + bc);
    };

    float acc[2][4][4];
    #pragma unroll
    for (int mi=0;mi<2;mi++)
        #pragma unroll
        for (int ni=0;ni<4;ni++)
            #pragma unroll
            for (int q=0;q<4;q++) acc[mi][ni][q]=0.f;

    const int m0 = (wid & 3) * 32;
    const int n0 = (wid >> 2) * 32;

    // ldmatrix per-lane offsets
    const int arow  = (lane & 7) + ((lane >> 3) & 1) * 8;
    const int akoff = (lane >> 4) * 8;
    const int brow  = (lane & 7) + ((lane >> 4) & 1) * 8;
    const int bkoff = ((lane >> 3) & 1) * 8;

    issue(0, 0); CP_COMMIT();

    const int NCH = 48;
    for (int ch = 0; ch < NCH; ch++){
        int buf = ch & 1;
        if (ch + 1 < NCH){ issue(buf ^ 1, ch + 1); CP_COMMIT(); CP_WAIT(1); }
        else             { CP_WAIT(0); }
        __syncthreads();

        unsigned sa = buf ? sA1 : sA0;
        unsigned sb = buf ? sB1 : sB0;
        #pragma unroll
        for (int ks = 0; ks < 32; ks += 16){
            unsigned af[2][4], bf[2][4];
            #pragma unroll
            for (int mi=0;mi<2;mi++)
                ldmx4(af[mi], sa + (unsigned)((m0 + mi*16 + arow)*VK_STR + ks + akoff)*2);
            #pragma unroll
            for (int g=0; g<2; g++)
                ldmx4(bf[g], sb + (unsigned)((n0 + g*16 + brow)*VK_STR + ks + bkoff)*2);
            #pragma unroll
            for (int mi=0;mi<2;mi++)
                #pragma unroll
                for (int ni=0;ni<4;ni++)
                    mma16816(acc[mi][ni], af[mi], bf[ni>>1][(ni&1)*2], bf[ni>>1][(ni&1)*2+1]);
        }
        __syncthreads();
    }

    // epilogue: direct to global + bias
    #pragma unroll
    for (int mi=0;mi<2;mi++){
        #pragma unroll
        for (int ni=0;ni<4;ni++){
            int row = mtile*128 + m0 + mi*16 + (lane >> 2);
            int col = ntile*64  + n0 + ni*8  + (lane & 3)*2;
            float bia0 = b_o[col], bia1 = b_o[col+1];
            if (row < T1*BB){
                float* o = logits + (size_t)row*VV + col;
                o[0] = acc[mi][ni][0] + bia0;
                o[1] = acc[mi][ni][1] + bia1;
            }
            if (row + 8 < T1*BB){
                float* o = logits + (size_t)(row+8)*VV + col;
                o[0] = acc[mi][ni][2] + bia0;
                o[1] = acc[mi][ni][3] + bia1;
            }
        }
    }
}

// ---------------------------------------------------------------------------
// Online log-softmax + argmax (FMA exp)
// ---------------------------------------------------------------------------
__global__ void k_lsm(float* __restrict__ logits)
{
    __shared__ float ms[256], ss[256];
    __shared__ int   ii[256];
    const int row = blockIdx.x;
    const int tid = threadIdx.x;
    float* x = logits + (size_t)row * VV;

    float m = x[tid]; float s = 1.f; int mi = tid;
    for (int c = tid + 256; c < VV; c += 256){
        float v = x[c];
        if (v > m){ s = s*fexp(m - v) + 1.f; m = v; mi = c; }
        else       s += fexp(v - m);
    }
    ms[tid]=m; ss[tid]=s; ii[tid]=mi;
    __syncthreads();
    for (int st = 128; st > 0; st >>= 1){
        if (tid < st){
            float m1=ms[tid], s1=ss[tid]; int i1=ii[tid];
            float m2=ms[tid+st], s2=ss[tid+st]; int i2=ii[tid+st];
            if (m2 > m1)      { ms[tid]=m2; ss[tid]=s1*fexp(m1-m2)+s2; ii[tid]=i2; }
            else if (m2 < m1) { ss[tid]=s1+s2*fexp(m2-m1); }
            else              { ss[tid]=s1+s2; ii[tid]=min(i1,i2); }
        }
        __syncthreads();
    }
    float lse = ms[0] + logf(ss[0]);
    if (tid == 0) g_argmax[row] = ii[0];
    for (int c = tid; c < VV; c += 256) x[c] -= lse;
}

__global__ void k_tail_f(float* __restrict__ out)
{
    int r = blockIdx.x*blockDim.x + threadIdx.x;
    if (r < T1*BB) out[TBV + r] = (float)g_argmax[r];
}
__global__ void k_tail_i(int* __restrict__ out)
{
    int r = blockIdx.x*blockDim.x + threadIdx.x;
    if (r < T1*BB) out[r] = g_argmax[r];
}

// ---------------------------------------------------------------------------
extern "C" void kernel_launch(void* const* d_in, const int* in_sizes, int n_in,
                              void* d_out, int out_size)
{
    const int*   tgt   = (const int*)  d_in[0];
    const int*   lens  = (const int*)  d_in[1];
    const float* enc   = (const float*)d_in[2];
    const float* h0    = (const float*)d_in[3];
    const float* c0    = (const float*)d_in[4];
    const float* emb   = (const float*)d_in[5];
    const float* W_ih  = (const float*)d_in[6];
    const float* W_hh  = (const float*)d_in[7];
    const float* b_ih  = (const float*)d_in[8];
    const float* b_hh  = (const float*)d_in[9];
    const float* W_a   = (const float*)d_in[10];
    const float* W_c   = (const float*)d_in[11];
    const float* b_c   = (const float*)d_in[12];
    const float* W_o   = (const float*)d_in[13];
    const float* b_o   = (const float*)d_in[14];

    float *p_proj=nullptr, *p_aha=nullptr, *p_lg=nullptr, *p_zero=nullptr;
    cudaGetSymbolAddress((void**)&p_proj, g_proj);
    cudaGetSymbolAddress((void**)&p_aha,  g_ah_all);
    cudaGetSymbolAddress((void**)&p_lg,   g_logits);
    cudaGetSymbolAddress((void**)&p_zero, g_zero);

    const bool big = (size_t)out_size >= TBV;
    float* logits = big ? (float*)d_out : p_lg;

    k_init<<<64, 256>>>(h0, c0);

    // bf16 split of W_o (independent of the recurrence)
    k_convW<<<(int)(((size_t)VV*HH/4 + 255)/256), 256>>>(W_o);

    // proj = enc @ W_a^T : [2048, 512]
    sgemm<64,64,16,4,4><<<dim3(512/64, 2048/64), 256>>>(
        enc, W_a, p_proj, BB*SS, HH, HH);

    for (int t = 0; t < T1; t++) {
        const float* ahp = (t == 0) ? p_zero : (p_aha + (size_t)(t-1)*BH);
        k_gates<<<dim3(4*HH/64, 1, 6), 256>>>(tgt, emb, W_ih, W_hh, ahp, t);
        k_step<<<BB, HH>>>(b_ih, b_hh, lens, enc, W_c, b_c, t);
    }

    // bf16 split of A (padded to 1024 rows)
    k_convA<<<(MPAD*HH/4 + 255)/256, 256>>>();

    // tensor-core (HMMA) vocab GEMM
    k_vocab<<<dim3(8, 500), 256>>>(b_o, logits);

    // online log-softmax + argmax
    k_lsm<<<T1*BB, 256>>>(logits);

    if (big && (size_t)out_size >= TBV + (size_t)T1*BB) {
        k_tail_f<<<4, 256>>>((float*)d_out);
    } else if (!big) {
        k_tail_i<<<4, 256>>>((int*)d_out);
    }
}

// round 5
// speedup vs baseline: 2.1615x; 2.1615x over previous
#include <cuda_runtime.h>
#include <cuda_bf16.h>
#include <math.h>

// Problem constants
#define BB 32
#define TT 32
#define SS 64
#define HH 512
#define EE 512
#define VV 32000
#define T1 (TT-1)
#define TBV ((size_t)T1*BB*VV)
#define BH (BB*HH)
#define MPAD 1024
#define KX 1536        // gates K = E + H + H
#define JG 2048        // gates outputs = 4H
#define GZ 8           // gates split-K factor

// -------- persistent device scratch --------
__device__ float g_h[BH];
__device__ float g_c[BH];
__device__ float g_proj[BB*SS*HH];
__device__ __align__(16) float g_XC[BB*1024];      // [b][h2(512)|ctx(512)]
__device__ float g_Gpart[GZ*BB*JG];                // gate partials
__device__ int   g_argmax[T1*BB];
__device__ float g_logits[T1*BB*VV];               // fallback, 127MB
__device__ __align__(16) __nv_bfloat16 g_Wh[(size_t)VV*HH];
__device__ __align__(16) __nv_bfloat16 g_Wl[(size_t)VV*HH];
__device__ __align__(16) __nv_bfloat16 g_Ah[MPAD*HH];   // rows 992..1023 stay 0
__device__ __align__(16) __nv_bfloat16 g_Al[MPAD*HH];
__device__ __align__(16) __nv_bfloat16 g_gWh[JG*KX];    // gate weights hi
__device__ __align__(16) __nv_bfloat16 g_gWl[JG*KX];    // gate weights lo
__device__ __align__(16) __nv_bfloat16 g_Xh[BB*KX];     // gates input hi
__device__ __align__(16) __nv_bfloat16 g_Xl[BB*KX];     // gates input lo

__device__ __forceinline__ float sigf(float x){ return 1.0f/(1.0f+expf(-x)); }

// fast exp via FMA polynomial (no MUFU in hot loops)
__device__ __forceinline__ float fexp(float x){
    float t = x * 1.4426950408889634f;
    float n = rintf(t);
    float f = t - n;
    float p = 1.5403530e-4f;
    p = fmaf(p, f, 1.3333558e-3f);
    p = fmaf(p, f, 9.6181291e-3f);
    p = fmaf(p, f, 5.5504109e-2f);
    p = fmaf(p, f, 2.4022651e-1f);
    p = fmaf(p, f, 6.9314718e-1f);
    p = fmaf(p, f, 1.0f);
    int e = (int)n;
    e = e < -126 ? -126 : (e > 127 ? 127 : e);
    float sc = __int_as_float((e+127)<<23);
    return p*sc;
}

// ------------------ low-level helpers (sm_80-compatible PTX) ------------------
__device__ __forceinline__ unsigned smem_u32(const void* p){
    unsigned a;
    asm("{ .reg .u64 t; cvta.to.shared.u64 t, %1; cvt.u32.u64 %0, t; }" : "=r"(a) : "l"(p));
    return a;
}
__device__ __forceinline__ void cpa16(unsigned dst, const void* src){
    asm volatile("cp.async.cg.shared.global [%0], [%1], 16;" :: "r"(dst), "l"(src));
}
#define CP_COMMIT() asm volatile("cp.async.commit_group;" ::: "memory")
#define CP_WAIT(n)  asm volatile("cp.async.wait_group %0;" :: "n"(n) : "memory")

__device__ __forceinline__ void ldmx4(unsigned* r, unsigned addr){
    asm volatile("ldmatrix.sync.aligned.m8n8.x4.shared.b16 {%0,%1,%2,%3}, [%4];"
        : "=r"(r[0]), "=r"(r[1]), "=r"(r[2]), "=r"(r[3]) : "r"(addr));
}
__device__ __forceinline__ void mma16816(float* d, const unsigned* a,
                                         unsigned b0, unsigned b1){
    asm volatile(
        "mma.sync.aligned.m16n8k16.row.col.f32.bf16.bf16.f32 "
        "{%0,%1,%2,%3}, {%4,%5,%6,%7}, {%8,%9}, {%0,%1,%2,%3};"
        : "+f"(d[0]), "+f"(d[1]), "+f"(d[2]), "+f"(d[3])
        : "r"(a[0]), "r"(a[1]), "r"(a[2]), "r"(a[3]), "r"(b0), "r"(b1));
}
__device__ __forceinline__ void bsplit(float v, __nv_bfloat16& hi, __nv_bfloat16& lo){
    hi = __float2bfloat16(v);
    lo = __float2bfloat16(v - __bfloat162float(hi));
}

// ---------------------------------------------------------------------------
// Generic tiled SGEMM (used only for proj precompute)
// ---------------------------------------------------------------------------
template<int BM,int BN,int BK,int TM,int TN>
__global__ void sgemm(const float* __restrict__ A, const float* __restrict__ B,
                      float* __restrict__ C, int M, int N, int K)
{
    constexpr int THREADS = (BM/TM)*(BN/TN);
    static_assert(THREADS == 256, "256 threads expected");
    __shared__ float As[BK][BM+4];
    __shared__ float Bs[BK][BN+4];
    const int tid = threadIdx.x;
    const int bm = blockIdx.y*BM, bn = blockIdx.x*BN;
    const int tx = tid % (BN/TN);
    const int ty = tid / (BN/TN);
    float acc[TM][TN];
    #pragma unroll
    for (int i=0;i<TM;i++)
        #pragma unroll
        for (int j=0;j<TN;j++) acc[i][j]=0.f;

    for (int k0 = 0; k0 < K; k0 += BK) {
        #pragma unroll
        for (int i=0;i<(BM*BK)/THREADS;i++){
            int idx = tid + i*THREADS; int m = idx/BK, k = idx%BK;
            As[k][m] = A[(size_t)(bm+m)*K + k0 + k];
        }
        #pragma unroll
        for (int i=0;i<(BN*BK)/THREADS;i++){
            int idx = tid + i*THREADS; int n = idx/BK, k = idx%BK;
            Bs[k][n] = B[(size_t)(bn+n)*K + k0 + k];
        }
        __syncthreads();
        #pragma unroll
        for (int kk=0;kk<BK;kk++){
            float a[TM], b[TN];
            #pragma unroll
            for (int i=0;i<TM;i++) a[i] = As[kk][ty*TM+i];
            #pragma unroll
            for (int j=0;j<TN;j++) b[j] = Bs[kk][tx*TN+j];
            #pragma unroll
            for (int i=0;i<TM;i++)
                #pragma unroll
                for (int j=0;j<TN;j++) acc[i][j] += a[i]*b[j];
        }
        __syncthreads();
    }
    #pragma unroll
    for (int i=0;i<TM;i++){
        int gm = bm + ty*TM + i;
        #pragma unroll
        for (int j=0;j<TN;j++)
            C[(size_t)gm*N + bn + tx*TN + j] = acc[i][j];
    }
}

// ---------------------------------------------------------------------------
// Prologue: h,c init + assemble X for step 0 (emb | 0 | h0), bf16 hi/lo
// grid 64 x 256 : one (b,k) pair per thread
// ---------------------------------------------------------------------------
__global__ void k_prep0(const float* __restrict__ h0, const float* __restrict__ c0,
                        const int* __restrict__ tgt, const float* __restrict__ emb)
{
    int idx = blockIdx.x*256 + threadIdx.x;     // 0..16383
    int b = idx >> 9, k = idx & 511;
    g_h[idx] = h0[idx];
    g_c[idx] = c0[idx];
    __nv_bfloat16 hi, lo;
    // emb part
    int w = tgt[b*TT + 0];
    bsplit(emb[(size_t)w*EE + k], hi, lo);
    g_Xh[b*KX + k] = hi;  g_Xl[b*KX + k] = lo;
    // ah part = 0
    g_Xh[b*KX + 512 + k] = __float2bfloat16(0.f);
    g_Xl[b*KX + 512 + k] = __float2bfloat16(0.f);
    // h part
    bsplit(h0[idx], hi, lo);
    g_Xh[b*KX + 1024 + k] = hi;  g_Xl[b*KX + 1024 + k] = lo;
}

// ---------------------------------------------------------------------------
// Gate weight conversion: gW[j][k] = [W_ih | W_hh] row j, bf16 hi/lo
// ---------------------------------------------------------------------------
__global__ void k_convG(const float* __restrict__ W_ih, const float* __restrict__ W_hh)
{
    size_t i = ((size_t)blockIdx.x*256 + threadIdx.x)*4;
    if (i >= (size_t)JG*KX) return;
    int j = (int)(i / KX);
    int k = (int)(i % KX);
    float4 v = (k < 1024) ? *(const float4*)(W_ih + (size_t)j*1024 + k)
                          : *(const float4*)(W_hh + (size_t)j*512 + (k-1024));
    __nv_bfloat16 h, l;
    bsplit(v.x, h, l); g_gWh[i+0]=h; g_gWl[i+0]=l;
    bsplit(v.y, h, l); g_gWh[i+1]=h; g_gWl[i+1]=l;
    bsplit(v.z, h, l); g_gWh[i+2]=h; g_gWl[i+2]=l;
    bsplit(v.w, h, l); g_gWh[i+3]=h; g_gWl[i+3]=l;
}

// ---------------------------------------------------------------------------
// Gates GEMM via HMMA, 3-term split precision.
// G[32, 2048] = X[32,1536] @ gW[2048,1536]^T   (partials per split-K z)
// grid (16 ntiles, 8 z), 256 threads. BM=32, BN=128, K/block = 192, BK=64.
// ---------------------------------------------------------------------------
#define GSTR 72   // smem row stride (bf16 elems) for 64-col chunk

__global__ void __launch_bounds__(256)
k_gmma()
{
    __shared__ __align__(16) __nv_bfloat16 sAh[32*GSTR];
    __shared__ __align__(16) __nv_bfloat16 sAl[32*GSTR];
    __shared__ __align__(16) __nv_bfloat16 sBh[128*GSTR];
    __shared__ __align__(16) __nv_bfloat16 sBl[128*GSTR];

    const int tid  = threadIdx.x;
    const int wid  = tid >> 5, lane = tid & 31;
    const int nt   = blockIdx.x;          // 0..15
    const int z    = blockIdx.y;          // 0..7
    const int nbase = nt * 128;
    const int kbase = z * 192;

    const unsigned uAh = smem_u32(sAh);
    const unsigned uAl = smem_u32(sAl);
    const unsigned uBh = smem_u32(sBh);
    const unsigned uBl = smem_u32(sBl);

    float acc[2][2][4];
    #pragma unroll
    for (int mi=0;mi<2;mi++)
        #pragma unroll
        for (int ni=0;ni<2;ni++)
            #pragma unroll
            for (int q=0;q<4;q++) acc[mi][ni][q]=0.f;

    const int n0 = wid * 16;
    const int arow  = (lane & 7) + ((lane >> 3) & 1) * 8;
    const int akoff = (lane >> 4) * 8;
    const int brow  = (lane & 7) + ((lane >> 4) & 1) * 8;
    const int bkoff = ((lane >> 3) & 1) * 8;

    for (int ck = 0; ck < 3; ck++){
        const int koff = kbase + ck*64;
        // load chunk: A(32x64) hi/lo + B(128x64) hi/lo = 2560 16B-chunks
        #pragma unroll
        for (int q = 0; q < 10; q++){
            int i = q*256 + tid;
            int row, c8;
            if (i < 512){
                int idx = i & 255; row = idx >> 3; c8 = idx & 7;
                const __nv_bfloat16* src = (i < 256 ? g_Xh : g_Xl)
                                           + (size_t)row*KX + koff + c8*8;
                unsigned dst = (i < 256 ? uAh : uAl) + (unsigned)(row*GSTR + c8*8)*2;
                cpa16(dst, src);
            } else {
                int idx = (i - 512) & 1023; row = idx >> 3; c8 = idx & 7;
                const __nv_bfloat16* src = (i < 1536 ? g_gWh : g_gWl)
                                           + (size_t)(nbase+row)*KX + koff + c8*8;
                unsigned dst = (i < 1536 ? uBh : uBl) + (unsigned)(row*GSTR + c8*8)*2;
                cpa16(dst, src);
            }
        }
        CP_COMMIT(); CP_WAIT(0);
        __syncthreads();

        #pragma unroll
        for (int ks = 0; ks < 64; ks += 16){
            unsigned afh[2][4], afl[2][4], bfh[4], bfl[4];
            #pragma unroll
            for (int mi=0;mi<2;mi++){
                ldmx4(afh[mi], uAh + (unsigned)((mi*16 + arow)*GSTR + ks + akoff)*2);
                ldmx4(afl[mi], uAl + (unsigned)((mi*16 + arow)*GSTR + ks + akoff)*2);
            }
            ldmx4(bfh, uBh + (unsigned)((n0 + brow)*GSTR + ks + bkoff)*2);
            ldmx4(bfl, uBl + (unsigned)((n0 + brow)*GSTR + ks + bkoff)*2);
            #pragma unroll
            for (int mi=0;mi<2;mi++)
                #pragma unroll
                for (int ni=0;ni<2;ni++){
                    mma16816(acc[mi][ni], afh[mi], bfh[ni*2], bfh[ni*2+1]);
                    mma16816(acc[mi][ni], afh[mi], bfl[ni*2], bfl[ni*2+1]);
                    mma16816(acc[mi][ni], afl[mi], bfh[ni*2], bfh[ni*2+1]);
                }
        }
        __syncthreads();
    }

    // write partials: Gpart[z][b][j]
    #pragma unroll
    for (int mi=0;mi<2;mi++){
        #pragma unroll
        for (int ni=0;ni<2;ni++){
            int row = mi*16 + (lane >> 2);
            int col = nbase + n0 + ni*8 + (lane & 3)*2;
            float* gp = g_Gpart + ((size_t)z*BB + row)*JG + col;
            gp[0]      = acc[mi][ni][0];
            gp[1]      = acc[mi][ni][1];
            gp += 8*JG;
            gp[0]      = acc[mi][ni][2];
            gp[1]      = acc[mi][ni][3];
        }
    }
}

// ---------------------------------------------------------------------------
// Fused LSTM cell + attention. 32 blocks x 512 threads.
// Writes: g_h, g_c, X h-part (bf16 hi/lo), g_XC = [h2|ctx] fp32.
// ---------------------------------------------------------------------------
__global__ void k_cell_attn(const float* __restrict__ b_ih, const float* __restrict__ b_hh,
                            const int* __restrict__ lens, const float* __restrict__ enc)
{
    __shared__ float hh[HH];
    __shared__ float sc[SS];
    const int b   = blockIdx.x;
    const int tid = threadIdx.x;
    const int len = lens[b];
    const int w = tid >> 5, l = tid & 31;

    // ---- LSTM cell: reduce 8 split-K partials ----
    float gv[4];
    #pragma unroll
    for (int q=0;q<4;q++){
        int j = q*HH + tid;
        float s = b_ih[j] + b_hh[j];
        #pragma unroll
        for (int z=0;z<GZ;z++) s += g_Gpart[((size_t)z*BB + b)*JG + j];
        gv[q] = s;
    }
    int idx = b*HH + tid;
    float ig = sigf(gv[0]);
    float fg = sigf(gv[1]);
    float gg = tanhf(gv[2]);
    float og = sigf(gv[3]);
    float c  = fg * g_c[idx] + ig * gg;
    g_c[idx] = c;
    float h2 = og * tanhf(c);
    g_h[idx] = h2;
    hh[tid] = h2;
    g_XC[b*1024 + tid] = h2;
    {   // X h-part for next step
        __nv_bfloat16 hi, lo; bsplit(h2, hi, lo);
        g_Xh[b*KX + 1024 + tid] = hi;
        g_Xl[b*KX + 1024 + tid] = lo;
    }
    __syncthreads();

    // ---- attention scores ----
    for (int s = w; s < SS; s += 16) {
        const float* pr = &g_proj[((size_t)s*BB + b)*HH];
        float sum = 0.f;
        for (int k = l; k < HH; k += 32) sum += hh[k] * pr[k];
        #pragma unroll
        for (int off=16; off>0; off>>=1) sum += __shfl_xor_sync(0xffffffffu, sum, off);
        if (l == 0) sc[s] = (s < len) ? sum : -1e9f;
    }
    __syncthreads();

    if (tid < 32) {
        float v0 = sc[tid], v1 = sc[tid+32];
        float m = fmaxf(v0, v1);
        #pragma unroll
        for (int off=16; off>0; off>>=1) m = fmaxf(m, __shfl_xor_sync(0xffffffffu, m, off));
        float e0 = expf(v0 - m), e1 = expf(v1 - m);
        float s = e0 + e1;
        #pragma unroll
        for (int off=16; off>0; off>>=1) s += __shfl_xor_sync(0xffffffffu, s, off);
        float inv = 1.0f / s;
        sc[tid]    = e0 * inv;
        sc[tid+32] = e1 * inv;
    }
    __syncthreads();

    // ---- context ----
    float acc = 0.f;
    #pragma unroll 4
    for (int s = 0; s < SS; s++)
        acc += sc[s] * enc[((size_t)s*BB + b)*HH + tid];
    g_XC[b*1024 + 512 + tid] = acc;
}

// ---------------------------------------------------------------------------
// ah2 = tanh(XC @ W_c^T + b_c) ; writes bf16 hi/lo directly into:
//   - vocab A buffers g_Ah/g_Al (row t*32+b)
//   - next step's X ah-part
// Also copies next step's emb slice into X.
// grid 64 blocks x 256 threads. Dynamic smem = 128KB for XC.
// Warp w of block nt handles output column c = nt*8 + w, W_c row in registers.
// ---------------------------------------------------------------------------
__global__ void __launch_bounds__(256)
k_ah2x(const float* __restrict__ W_c, const float* __restrict__ b_c,
       const int* __restrict__ tgt, const float* __restrict__ emb, int t)
{
    extern __shared__ float xc[];          // [32][1024]
    const int tid = threadIdx.x;
    const int w = tid >> 5, l = tid & 31;
    const int nt = blockIdx.x;

    // emb gather for step t+1 (independent work, do first)
    if (t < T1-1){
        int b2 = nt >> 1;
        int k2 = (nt & 1)*256 + tid;
        int wd = tgt[b2*TT + (t+1)];
        __nv_bfloat16 hi, lo;
        bsplit(emb[(size_t)wd*EE + k2], hi, lo);
        g_Xh[b2*KX + k2] = hi;
        g_Xl[b2*KX + k2] = lo;
    }

    // stage XC into smem (32768 floats)
    {
        const float4* src = (const float4*)g_XC;
        float4* dst = (float4*)xc;
        for (int i = tid; i < 8192; i += 256) dst[i] = src[i];
    }
    __syncthreads();

    // W_c row for this warp's column, held in registers
    const int c = nt*8 + w;
    const float* wr = W_c + (size_t)c*1024;
    float wreg[32];
    #pragma unroll
    for (int q=0;q<32;q++) wreg[q] = wr[l + q*32];
    float bias = b_c[c];

    for (int b = 0; b < BB; b++){
        const float* xb = xc + b*1024;
        float s = 0.f;
        #pragma unroll
        for (int q=0;q<32;q++) s += wreg[q] * xb[l + q*32];
        #pragma unroll
        for (int off=16; off>0; off>>=1) s += __shfl_xor_sync(0xffffffffu, s, off);
        if (l == 0){
            float v = tanhf(s + bias);
            __nv_bfloat16 hi, lo; bsplit(v, hi, lo);
            int r = t*BB + b;
            g_Ah[(size_t)r*HH + c] = hi;
            g_Al[(size_t)r*HH + c] = lo;
            g_Xh[b*KX + 512 + c] = hi;
            g_Xl[b*KX + 512 + c] = lo;
        }
    }
}

// ---------------------------------------------------------------------------
// bf16 split of W_o (unchanged, proven)
// ---------------------------------------------------------------------------
__global__ void k_convW(const float* __restrict__ W)
{
    size_t i = ((size_t)blockIdx.x*256 + threadIdx.x)*4;
    if (i >= (size_t)VV*HH) return;
    float4 v = *(const float4*)(W + i);
    __nv_bfloat16 h0, h1, h2, h3, l0, l1, l2, l3;
    bsplit(v.x, h0, l0); bsplit(v.y, h1, l1);
    bsplit(v.z, h2, l2); bsplit(v.w, h3, l3);
    *(__nv_bfloat162*)(g_Wh + i)     = __nv_bfloat162(h0, h1);
    *(__nv_bfloat162*)(g_Wh + i + 2) = __nv_bfloat162(h2, h3);
    *(__nv_bfloat162*)(g_Wl + i)     = __nv_bfloat162(l0, l1);
    *(__nv_bfloat162*)(g_Wl + i + 2) = __nv_bfloat162(l2, l3);
}

// ---------------------------------------------------------------------------
// Vocab GEMM via mma.sync (HMMA bf16, fp32 accum), 3-term split precision.
// (unchanged from the passing round-4 kernel)
// ---------------------------------------------------------------------------
#define VK_STR 40

__global__ void __launch_bounds__(256, 2)
k_vocab(const float* __restrict__ b_o, float* __restrict__ logits)
{
    __shared__ __align__(16) __nv_bfloat16 As[2][128*VK_STR];
    __shared__ __align__(16) __nv_bfloat16 Bs[2][64*VK_STR];
    const int tid  = threadIdx.x;
    const int wid  = tid >> 5, lane = tid & 31;
    const int mtile = blockIdx.x;   // 0..7
    const int ntile = blockIdx.y;   // 0..499

    const __nv_bfloat16* Ap[3] = { g_Ah + (size_t)mtile*128*HH,
                                   g_Ah + (size_t)mtile*128*HH,
                                   g_Al + (size_t)mtile*128*HH };
    const __nv_bfloat16* Bp[3] = { g_Wh + (size_t)ntile*64*HH,
                                   g_Wl + (size_t)ntile*64*HH,
                                   g_Wh + (size_t)ntile*64*HH };

    const unsigned sA0 = smem_u32(&As[0][0]);
    const unsigned sA1 = smem_u32(&As[1][0]);
    const unsigned sB0 = smem_u32(&Bs[0][0]);
    const unsigned sB1 = smem_u32(&Bs[1][0]);

    const int aid0 = tid, aid1 = tid + 256;
    const int ar0 = aid0 >> 2, ac0 = (aid0 & 3) * 8;
    const int ar1 = aid1 >> 2, ac1 = (aid1 & 3) * 8;
    const int br  = tid >> 2,  bc  = (tid & 3) * 8;

    auto issue = [&](int buf, int ch){
        int pass = ch >> 4;
        int k0   = (ch & 15) * 32;
        unsigned sa = buf ? sA1 : sA0;
        unsigned sb = buf ? sB1 : sB0;
        const __nv_bfloat16* a = Ap[pass] + k0;
        const __nv_bfloat16* bsrc = Bp[pass] + k0;
        cpa16(sa + (unsigned)(ar0*VK_STR + ac0)*2, a + (size_t)ar0*HH + ac0);
        cpa16(sa + (unsigned)(ar1*VK_STR + ac1)*2, a + (size_t)ar1*HH + ac1);
        cpa16(sb + (unsigned)(br *VK_STR + bc )*2, bsrc + (size_t)br*HH + bc);
    };

    float acc[2][4][4];
    #pragma unroll
    for (int mi=0;mi<2;mi++)
        #pragma unroll
        for (int ni=0;ni<4;ni++)
            #pragma unroll
            for (int q=0;q<4;q++) acc[mi][ni][q]=0.f;

    const int m0 = (wid & 3) * 32;
    const int n0 = (wid >> 2) * 32;

    const int arow  = (lane & 7) + ((lane >> 3) & 1) * 8;
    const int akoff = (lane >> 4) * 8;
    const int brow  = (lane & 7) + ((lane >> 4) & 1) * 8;
    const int bkoff = ((lane >> 3) & 1) * 8;

    issue(0, 0); CP_COMMIT();

    const int NCH = 48;
    for (int ch = 0; ch < NCH; ch++){
        int buf = ch & 1;
        if (ch + 1 < NCH){ issue(buf ^ 1, ch + 1); CP_COMMIT(); CP_WAIT(1); }
        else             { CP_WAIT(0); }
        __syncthreads();

        unsigned sa = buf ? sA1 : sA0;
        unsigned sb = buf ? sB1 : sB0;
        #pragma unroll
        for (int ks = 0; ks < 32; ks += 16){
            unsigned af[2][4], bf[2][4];
            #pragma unroll
            for (int mi=0;mi<2;mi++)
                ldmx4(af[mi], sa + (unsigned)((m0 + mi*16 + arow)*VK_STR + ks + akoff)*2);
            #pragma unroll
            for (int g=0; g<2; g++)
                ldmx4(bf[g], sb + (unsigned)((n0 + g*16 + brow)*VK_STR + ks + bkoff)*2);
            #pragma unroll
            for (int mi=0;mi<2;mi++)
                #pragma unroll
                for (int ni=0;ni<4;ni++)
                    mma16816(acc[mi][ni], af[mi], bf[ni>>1][(ni&1)*2], bf[ni>>1][(ni&1)*2+1]);
        }
        __syncthreads();
    }

    #pragma unroll
    for (int mi=0;mi<2;mi++){
        #pragma unroll
        for (int ni=0;ni<4;ni++){
            int row = mtile*128 + m0 + mi*16 + (lane >> 2);
            int col = ntile*64  + n0 + ni*8  + (lane & 3)*2;
            float bia0 = b_o[col], bia1 = b_o[col+1];
            if (row < T1*BB){
                float* o = logits + (size_t)row*VV + col;
                o[0] = acc[mi][ni][0] + bia0;
                o[1] = acc[mi][ni][1] + bia1;
            }
            if (row + 8 < T1*BB){
                float* o = logits + (size_t)(row+8)*VV + col;
                o[0] = acc[mi][ni][2] + bia0;
                o[1] = acc[mi][ni][3] + bia1;
            }
        }
    }
}

// ---------------------------------------------------------------------------
// Online log-softmax + argmax (FMA exp)
// ---------------------------------------------------------------------------
__global__ void k_lsm(float* __restrict__ logits)
{
    __shared__ float ms[256], ss[256];
    __shared__ int   ii[256];
    const int row = blockIdx.x;
    const int tid = threadIdx.x;
    float* x = logits + (size_t)row * VV;

    float m = x[tid]; float s = 1.f; int mi = tid;
    for (int c = tid + 256; c < VV; c += 256){
        float v = x[c];
        if (v > m){ s = s*fexp(m - v) + 1.f; m = v; mi = c; }
        else       s += fexp(v - m);
    }
    ms[tid]=m; ss[tid]=s; ii[tid]=mi;
    __syncthreads();
    for (int st = 128; st > 0; st >>= 1){
        if (tid < st){
            float m1=ms[tid], s1=ss[tid]; int i1=ii[tid];
            float m2=ms[tid+st], s2=ss[tid+st]; int i2=ii[tid+st];
            if (m2 > m1)      { ms[tid]=m2; ss[tid]=s1*fexp(m1-m2)+s2; ii[tid]=i2; }
            else if (m2 < m1) { ss[tid]=s1+s2*fexp(m2-m1); }
            else              { ss[tid]=s1+s2; ii[tid]=min(i1,i2); }
        }
        __syncthreads();
    }
    float lse = ms[0] + logf(ss[0]);
    if (tid == 0) g_argmax[row] = ii[0];
    for (int c = tid; c < VV; c += 256) x[c] -= lse;
}

__global__ void k_tail_f(float* __restrict__ out)
{
    int r = blockIdx.x*blockDim.x + threadIdx.x;
    if (r < T1*BB) out[TBV + r] = (float)g_argmax[r];
}
__global__ void k_tail_i(int* __restrict__ out)
{
    int r = blockIdx.x*blockDim.x + threadIdx.x;
    if (r < T1*BB) out[r] = g_argmax[r];
}

// ---------------------------------------------------------------------------
extern "C" void kernel_launch(void* const* d_in, const int* in_sizes, int n_in,
                              void* d_out, int out_size)
{
    const int*   tgt   = (const int*)  d_in[0];
    const int*   lens  = (const int*)  d_in[1];
    const float* enc   = (const float*)d_in[2];
    const float* h0    = (const float*)d_in[3];
    const float* c0    = (const float*)d_in[4];
    const float* emb   = (const float*)d_in[5];
    const float* W_ih  = (const float*)d_in[6];
    const float* W_hh  = (const float*)d_in[7];
    const float* b_ih  = (const float*)d_in[8];
    const float* b_hh  = (const float*)d_in[9];
    const float* W_a   = (const float*)d_in[10];
    const float* W_c   = (const float*)d_in[11];
    const float* b_c   = (const float*)d_in[12];
    const float* W_o   = (const float*)d_in[13];
    const float* b_o   = (const float*)d_in[14];

    float *p_proj=nullptr, *p_lg=nullptr;
    cudaGetSymbolAddress((void**)&p_proj, g_proj);
    cudaGetSymbolAddress((void**)&p_lg,   g_logits);

    const bool big = (size_t)out_size >= TBV;
    float* logits = big ? (float*)d_out : p_lg;

    cudaFuncSetAttribute(k_ah2x, cudaFuncAttributeMaxDynamicSharedMemorySize, 131072);

    // prologue
    k_prep0<<<64, 256>>>(h0, c0, tgt, emb);
    k_convW<<<(int)(((size_t)VV*HH/4 + 255)/256), 256>>>(W_o);
    k_convG<<<(int)(((size_t)JG*KX/4 + 255)/256), 256>>>(W_ih, W_hh);
    sgemm<64,64,16,4,4><<<dim3(512/64, 2048/64), 256>>>(
        enc, W_a, p_proj, BB*SS, HH, HH);

    // 31 recurrent steps, 3 kernels each
    for (int t = 0; t < T1; t++) {
        k_gmma<<<dim3(16, GZ), 256>>>();
        k_cell_attn<<<BB, HH>>>(b_ih, b_hh, lens, enc);
        k_ah2x<<<64, 256, 131072>>>(W_c, b_c, tgt, emb, t);
    }

    // vocab projection (HMMA) + log-softmax
    k_vocab<<<dim3(8, 500), 256>>>(b_o, logits);
    k_lsm<<<T1*BB, 256>>>(logits);

    if (big && (size_t)out_size >= TBV + (size_t)T1*BB) {
        k_tail_f<<<4, 256>>>((float*)d_out);
    } else if (!big) {
        k_tail_i<<<4, 256>>>((int*)d_out);
    }
}